// round 1
// baseline (speedup 1.0000x reference)
#include <cuda_runtime.h>
#include <cuda_bf16.h>
#include <mma.h>
#include <cstdint>

using namespace nvcuda;

// Problem constants
#define TOKENS 4096
#define DMODEL 1024
#define VOCAB  32000
#define KSEL   128

// GEMM tiling
#define BM 128
#define BN 64
#define BKK 16   // k-tile (two wmma k=8 steps)

// Scratch: dot products [TOKENS, VOCAB] fp32 (512MB) as static device global (no allocs allowed)
static __device__ float g_scratch[(size_t)TOKENS * VOCAB];
static __device__ float g_xsq[TOKENS];
static __device__ float g_bsq[VOCAB];

// ---------------------------------------------------------------------------
// Row squared-norm kernel: one block per row, D=1024, 256 threads (1 float4 each)
// ---------------------------------------------------------------------------
__global__ void rowsq_kernel(const float* __restrict__ src, float* __restrict__ sq, int D) {
    __shared__ float warp_sums[8];
    int row = blockIdx.x;
    int tid = threadIdx.x;
    const float* s = src + (size_t)row * D;

    float acc = 0.f;
    for (int j = tid * 4; j < D; j += blockDim.x * 4) {
        float4 v = *(const float4*)&s[j];
        acc += v.x * v.x + v.y * v.y + v.z * v.z + v.w * v.w;
    }
    // warp reduce
    #pragma unroll
    for (int off = 16; off > 0; off >>= 1)
        acc += __shfl_xor_sync(0xFFFFFFFFu, acc, off);
    if ((tid & 31) == 0) warp_sums[tid >> 5] = acc;
    __syncthreads();
    if (tid == 0) {
        float total = 0.f;
        #pragma unroll
        for (int w = 0; w < 8; w++) total += warp_sums[w];
        sq[row] = total;
    }
}

// ---------------------------------------------------------------------------
// TF32 WMMA GEMM: C[t,v] = dot(x[t,:], W[v,:])
// Block computes BM x BN. 8 warps laid out 4 (M) x 2 (N), each warp 32x32.
// blockIdx.x -> token tile (32), blockIdx.y -> vocab tile (500):
// W streams once; x tile set stays hot in L2.
// ---------------------------------------------------------------------------
__global__ void __launch_bounds__(256) gemm_tf32_kernel(
    const float* __restrict__ A,   // [TOKENS, DMODEL]
    const float* __restrict__ B,   // [VOCAB, DMODEL]
    float* __restrict__ C          // [TOKENS, VOCAB]
) {
    __shared__ float As[BM][BKK + 4];
    __shared__ float Bs[BN][BKK + 4];

    const int bm = blockIdx.x;   // 0..31
    const int bn = blockIdx.y;   // 0..499
    const int tid = threadIdx.x;
    const int warp = tid >> 5;
    const int wm = warp & 3;     // 0..3 (rows of 32)
    const int wn = warp >> 2;    // 0..1 (cols of 32)

    wmma::fragment<wmma::accumulator, 16, 16, 8, float> acc[2][2];
    #pragma unroll
    for (int i = 0; i < 2; i++)
        #pragma unroll
        for (int j = 0; j < 2; j++)
            wmma::fill_fragment(acc[i][j], 0.0f);

    for (int k0 = 0; k0 < DMODEL; k0 += BKK) {
        // Load A tile: 128x16 floats = 512 float4, 2 per thread
        #pragma unroll
        for (int i = 0; i < 2; i++) {
            int idx = tid + i * 256;          // 0..511
            int r = idx >> 2;                 // 4 float4 per row
            int c = (idx & 3) * 4;
            *(float4*)&As[r][c] =
                *(const float4*)&A[(size_t)(bm * BM + r) * DMODEL + k0 + c];
        }
        // Load B tile: 64x16 floats = 256 float4, 1 per thread
        {
            int r = tid >> 2;
            int c = (tid & 3) * 4;
            *(float4*)&Bs[r][c] =
                *(const float4*)&B[(size_t)(bn * BN + r) * DMODEL + k0 + c];
        }
        __syncthreads();

        #pragma unroll
        for (int kk = 0; kk < BKK; kk += 8) {
            wmma::fragment<wmma::matrix_a, 16, 16, 8, wmma::precision::tf32, wmma::row_major> af[2];
            wmma::fragment<wmma::matrix_b, 16, 16, 8, wmma::precision::tf32, wmma::col_major> bf[2];
            #pragma unroll
            for (int i = 0; i < 2; i++) {
                wmma::load_matrix_sync(af[i], &As[wm * 32 + i * 16][kk], BKK + 4);
                #pragma unroll
                for (int t = 0; t < af[i].num_elements; t++)
                    af[i].x[t] = wmma::__float_to_tf32(af[i].x[t]);
            }
            #pragma unroll
            for (int j = 0; j < 2; j++) {
                wmma::load_matrix_sync(bf[j], &Bs[wn * 32 + j * 16][kk], BKK + 4);
                #pragma unroll
                for (int t = 0; t < bf[j].num_elements; t++)
                    bf[j].x[t] = wmma::__float_to_tf32(bf[j].x[t]);
            }
            #pragma unroll
            for (int i = 0; i < 2; i++)
                #pragma unroll
                for (int j = 0; j < 2; j++)
                    wmma::mma_sync(acc[i][j], af[i], bf[j], acc[i][j]);
        }
        __syncthreads();
    }

    #pragma unroll
    for (int i = 0; i < 2; i++)
        #pragma unroll
        for (int j = 0; j < 2; j++) {
            size_t row = (size_t)(bm * BM + wm * 32 + i * 16);
            size_t col = (size_t)(bn * BN + wn * 32 + j * 16);
            wmma::store_matrix_sync(&C[row * VOCAB + col], acc[i][j], VOCAB,
                                    wmma::mem_row_major);
        }
}

// ---------------------------------------------------------------------------
// Per-row top-128-smallest via 4-pass radix select + gather + bitonic sort.
// dist = xsq[t] - 2*dot + bsq[v] is recomputed on the fly (deterministic fp).
// Key transform: monotone uint mapping of float (handles any sign).
// ---------------------------------------------------------------------------
__device__ __forceinline__ unsigned int flip_key(float f) {
    unsigned int u = __float_as_uint(f);
    return u ^ ((u & 0x80000000u) ? 0xFFFFFFFFu : 0x80000000u);
}

__global__ void __launch_bounds__(256) topk_kernel(
    const float* __restrict__ S,     // dot products [TOKENS, VOCAB]
    const float* __restrict__ xsq,   // [TOKENS]
    const float* __restrict__ bsq,   // [VOCAB]
    float* __restrict__ out          // [TOKENS, KSEL]
) {
    __shared__ unsigned int hist[256];
    __shared__ float buf[KSEL];
    __shared__ unsigned int sh_digit, sh_cumless;
    __shared__ unsigned int cLess, cEq;

    const int t = blockIdx.x;
    const int tid = threadIdx.x;
    const float* srow = S + (size_t)t * VOCAB;
    const float xs = xsq[t];

    unsigned int prefix = 0;
    int remaining = KSEL;

    // 4 radix passes, 8 bits each, high to low
    for (int shift = 24; shift >= 0; shift -= 8) {
        for (int i = tid; i < 256; i += 256) hist[i] = 0;
        __syncthreads();

        for (int j = tid; j < VOCAB; j += 256) {
            float dist = fmaf(-2.0f, srow[j], xs + __ldg(&bsq[j]));
            unsigned int u = flip_key(dist);
            bool match = (shift == 24) || ((u >> (shift + 8)) == prefix);
            if (match) atomicAdd(&hist[(u >> shift) & 255u], 1u);
        }
        __syncthreads();

        if (tid == 0) {
            unsigned int cum = 0, d = 0;
            for (d = 0; d < 256; d++) {
                unsigned int c = hist[d];
                if (cum + c >= (unsigned int)remaining) break;
                cum += c;
            }
            sh_digit = d;
            sh_cumless = cum;
        }
        __syncthreads();
        remaining -= (int)sh_cumless;
        prefix = (prefix << 8) | sh_digit;
        __syncthreads();
    }

    // prefix == key of the K-th smallest; remaining == # of equal keys to take
    if (tid == 0) { cLess = 0; cEq = 0; }
    __syncthreads();

    const unsigned int nless = (unsigned int)(KSEL - remaining);
    for (int j = tid; j < VOCAB; j += 256) {
        float dist = fmaf(-2.0f, srow[j], xs + __ldg(&bsq[j]));
        unsigned int u = flip_key(dist);
        if (u < prefix) {
            unsigned int p = atomicAdd(&cLess, 1u);
            buf[p] = dist;
        } else if (u == prefix) {
            unsigned int e = atomicAdd(&cEq, 1u);
            if (e < (unsigned int)remaining) buf[nless + e] = dist;
        }
    }
    __syncthreads();

    // Bitonic sort 128 floats ascending (threads 0..127 active)
    for (int ksz = 2; ksz <= KSEL; ksz <<= 1) {
        for (int j2 = ksz >> 1; j2 > 0; j2 >>= 1) {
            if (tid < KSEL) {
                int ixj = tid ^ j2;
                if (ixj > tid) {
                    float a = buf[tid];
                    float b = buf[ixj];
                    bool up = ((tid & ksz) == 0);
                    if ((a > b) == up) { buf[tid] = b; buf[ixj] = a; }
                }
            }
            __syncthreads();
        }
    }

    if (tid < KSEL) out[(size_t)t * KSEL + tid] = buf[tid];
}

// ---------------------------------------------------------------------------
// Launch
// ---------------------------------------------------------------------------
extern "C" void kernel_launch(void* const* d_in, const int* in_sizes, int n_in,
                              void* d_out, int out_size) {
    const float* x = (const float*)d_in[0];   // [4096, 1024]
    const float* w = (const float*)d_in[1];   // [32000, 1024]
    float* out = (float*)d_out;               // [4096, 128]

    float *scr, *xsq, *bsq;
    cudaGetSymbolAddress((void**)&scr, g_scratch);
    cudaGetSymbolAddress((void**)&xsq, g_xsq);
    cudaGetSymbolAddress((void**)&bsq, g_bsq);

    rowsq_kernel<<<TOKENS, 256>>>(x, xsq, DMODEL);
    rowsq_kernel<<<VOCAB, 256>>>(w, bsq, DMODEL);

    dim3 grid(TOKENS / BM, VOCAB / BN);  // (32, 500)
    gemm_tf32_kernel<<<grid, 256>>>(x, w, scr);

    topk_kernel<<<TOKENS, 256>>>(scr, xsq, bsq, out);
}

// round 2
// speedup vs baseline: 2.7329x; 2.7329x over previous
#include <cuda_runtime.h>
#include <cuda_bf16.h>
#include <mma.h>
#include <cstdint>

using namespace nvcuda;

#define TOKENS 4096
#define DMODEL 1024
#define VOCAB  32000
#define KSEL   128

// GEMM tiling
#define BM 128
#define BN 128
#define BK 32
#define PAD 8
#define LDS (BK + PAD)          // 40 bf16 elems per row (80B, 16B-aligned)
#define NT (DMODEL / BK)        // 32 k-tiles

// Device scratch (no allocations allowed)
static __device__ float g_dist[(size_t)TOKENS * VOCAB];      // 512MB distances
static __device__ __nv_bfloat16 g_xb[(size_t)TOKENS * DMODEL];
static __device__ __nv_bfloat16 g_wb[(size_t)VOCAB * DMODEL];
static __device__ float g_xsq[TOKENS];
static __device__ float g_bsq[VOCAB];

// ---------------------------------------------------------------------------
// fp32 -> bf16 conversion (elementwise, 8B stores)
// ---------------------------------------------------------------------------
__global__ void convert_bf16_kernel(const float* __restrict__ src,
                                    __nv_bfloat16* __restrict__ dst, size_t n4) {
    size_t i = (size_t)blockIdx.x * blockDim.x + threadIdx.x;
    if (i >= n4) return;
    float4 v = *(const float4*)&src[i * 4];
    __nv_bfloat162 lo = __floats2bfloat162_rn(v.x, v.y);
    __nv_bfloat162 hi = __floats2bfloat162_rn(v.z, v.w);
    uint2 packed;
    packed.x = *(uint32_t*)&lo;
    packed.y = *(uint32_t*)&hi;
    *(uint2*)&dst[i * 4] = packed;
}

// ---------------------------------------------------------------------------
// Row squared norms (fp32 exact), one block per row
// ---------------------------------------------------------------------------
__global__ void rowsq_kernel(const float* __restrict__ src, float* __restrict__ sq, int D) {
    __shared__ float warp_sums[8];
    int row = blockIdx.x;
    int tid = threadIdx.x;
    const float* s = src + (size_t)row * D;
    float acc = 0.f;
    for (int j = tid * 4; j < D; j += blockDim.x * 4) {
        float4 v = *(const float4*)&s[j];
        acc += v.x * v.x + v.y * v.y + v.z * v.z + v.w * v.w;
    }
    #pragma unroll
    for (int off = 16; off > 0; off >>= 1)
        acc += __shfl_xor_sync(0xFFFFFFFFu, acc, off);
    if ((tid & 31) == 0) warp_sums[tid >> 5] = acc;
    __syncthreads();
    if (tid == 0) {
        float total = 0.f;
        #pragma unroll
        for (int w = 0; w < 8; w++) total += warp_sums[w];
        sq[row] = total;
    }
}

// ---------------------------------------------------------------------------
// cp.async helpers
// ---------------------------------------------------------------------------
__device__ __forceinline__ void cp_async16(void* smem, const void* gmem) {
    uint32_t s = (uint32_t)__cvta_generic_to_shared(smem);
    asm volatile("cp.async.cg.shared.global [%0], [%1], 16;\n" :: "r"(s), "l"(gmem));
}
__device__ __forceinline__ void cp_commit() {
    asm volatile("cp.async.commit_group;\n" ::);
}
template <int N>
__device__ __forceinline__ void cp_wait() {
    asm volatile("cp.async.wait_group %0;\n" :: "n"(N));
}

// ---------------------------------------------------------------------------
// bf16 WMMA GEMM with fused distance epilogue:
//   dist[t,v] = xsq[t] + bsq[v] - 2 * dot(x[t], w[v])
// Block tile 128x128, BK=32, double-buffered cp.async.
// 8 warps: 2 (M) x 4 (N), warp tile 64x32.
// ---------------------------------------------------------------------------
__global__ void __launch_bounds__(256) gemm_dist_kernel(
    const __nv_bfloat16* __restrict__ A,   // [TOKENS, DMODEL]
    const __nv_bfloat16* __restrict__ B,   // [VOCAB, DMODEL]
    const float* __restrict__ xsq,
    const float* __restrict__ bsq,
    float* __restrict__ C                  // [TOKENS, VOCAB] distances
) {
    // manual smem layout: As[2] (20KB) | Bs[2] (20KB) | xs_s (512B) | bs_s (512B)
    __shared__ __align__(16) char sm[2 * BM * LDS * 2 + 2 * BN * LDS * 2 + 1024];
    __nv_bfloat16* AsBase = (__nv_bfloat16*)sm;
    __nv_bfloat16* BsBase = (__nv_bfloat16*)(sm + 2 * BM * LDS * 2);
    float* xs_s = (float*)(sm + 2 * BM * LDS * 2 + 2 * BN * LDS * 2);
    float* bs_s = xs_s + BM;
    // epilogue staging aliases the As region (used only after final sync)
    float* stg = (float*)sm;   // per-warp 16x20 fp32

    const int bm = blockIdx.x;   // 0..31 token tile
    const int bn = blockIdx.y;   // 0..249 vocab tile
    const int tid = threadIdx.x;
    const int warp = tid >> 5;
    const int lane = tid & 31;
    const int wm = warp & 1;     // 0..1
    const int wn = warp >> 1;    // 0..3

    const int row0 = bm * BM;
    const int col0 = bn * BN;

    if (tid < BM) xs_s[tid] = xsq[row0 + tid];
    if (tid < BN) bs_s[tid] = bsq[col0 + tid];

    wmma::fragment<wmma::accumulator, 16, 16, 16, float> acc[4][2];
    #pragma unroll
    for (int i = 0; i < 4; i++)
        #pragma unroll
        for (int j = 0; j < 2; j++)
            wmma::fill_fragment(acc[i][j], 0.0f);

    auto asPtr = [&](int stage, int r, int c) -> __nv_bfloat16* {
        return AsBase + (size_t)stage * BM * LDS + r * LDS + c;
    };
    auto bsPtr = [&](int stage, int r, int c) -> __nv_bfloat16* {
        return BsBase + (size_t)stage * BN * LDS + r * LDS + c;
    };

    auto issue_loads = [&](int stage, int k0) {
        // A: 128x32 bf16 = 512 x 16B chunks; 2 per thread
        #pragma unroll
        for (int i = 0; i < 2; i++) {
            int c = tid + i * 256;
            int r = c >> 2;
            int cc = (c & 3) * 8;
            cp_async16(asPtr(stage, r, cc),
                       A + (size_t)(row0 + r) * DMODEL + k0 + cc);
        }
        // B: 128x32
        #pragma unroll
        for (int i = 0; i < 2; i++) {
            int c = tid + i * 256;
            int r = c >> 2;
            int cc = (c & 3) * 8;
            cp_async16(bsPtr(stage, r, cc),
                       B + (size_t)(col0 + r) * DMODEL + k0 + cc);
        }
        cp_commit();
    };

    issue_loads(0, 0);

    for (int kt = 0; kt < NT; kt++) {
        int stage = kt & 1;
        if (kt + 1 < NT) {
            issue_loads((kt + 1) & 1, (kt + 1) * BK);
            cp_wait<1>();
        } else {
            cp_wait<0>();
        }
        __syncthreads();

        #pragma unroll
        for (int kk = 0; kk < BK; kk += 16) {
            wmma::fragment<wmma::matrix_a, 16, 16, 16, __nv_bfloat16, wmma::row_major> af[4];
            wmma::fragment<wmma::matrix_b, 16, 16, 16, __nv_bfloat16, wmma::col_major> bf[2];
            #pragma unroll
            for (int mi = 0; mi < 4; mi++)
                wmma::load_matrix_sync(af[mi], asPtr(stage, wm * 64 + mi * 16, kk), LDS);
            #pragma unroll
            for (int ni = 0; ni < 2; ni++)
                wmma::load_matrix_sync(bf[ni], bsPtr(stage, wn * 32 + ni * 16, kk), LDS);
            #pragma unroll
            for (int mi = 0; mi < 4; mi++)
                #pragma unroll
                for (int ni = 0; ni < 2; ni++)
                    wmma::mma_sync(acc[mi][ni], af[mi], bf[ni], acc[mi][ni]);
        }
        __syncthreads();
    }

    // Epilogue: per-warp staging, apply dist transform, write out.
    float* mystg = stg + warp * 16 * 20;
    #pragma unroll
    for (int mi = 0; mi < 4; mi++) {
        #pragma unroll
        for (int ni = 0; ni < 2; ni++) {
            wmma::store_matrix_sync(mystg, acc[mi][ni], 20, wmma::mem_row_major);
            __syncwarp();
            int r = lane >> 1;
            int cb = (lane & 1) * 8;
            int grow = wm * 64 + mi * 16 + r;
            int gcol = wn * 32 + ni * 16 + cb;
            float base = xs_s[grow];
            float4 o0, o1;
            float* op = (float*)&o0;
            #pragma unroll
            for (int c = 0; c < 8; c++) {
                float dot = mystg[r * 20 + cb + c];
                ((c < 4) ? ((float*)&o0)[c] : ((float*)&o1)[c - 4]) =
                    fmaf(-2.0f, dot, base + bs_s[gcol + c]);
            }
            (void)op;
            float* dst = &C[(size_t)(row0 + grow) * VOCAB + col0 + gcol];
            *(float4*)dst = o0;
            *(float4*)(dst + 4) = o1;
            __syncwarp();
        }
    }
}

// ---------------------------------------------------------------------------
// Top-128-smallest per row over dist[VOCAB].
// Level-0: 4096-bin histogram on key bits [31:20]; gather all candidates with
// (key>>20) <= P into smem (typically ~300), bitonic sort, emit 128.
// Falls back to finer refinement levels if a bin is pathologically full.
// ---------------------------------------------------------------------------
__device__ __forceinline__ unsigned int flip_key(float f) {
    unsigned int u = __float_as_uint(f);
    return u ^ ((u & 0x80000000u) ? 0xFFFFFFFFu : 0x80000000u);
}

#define TK_BINS 4096
#define TK_CAP  4096

__global__ void __launch_bounds__(256) topk_kernel(
    const float* __restrict__ S,     // distances [TOKENS, VOCAB]
    float* __restrict__ out          // [TOKENS, KSEL]
) {
    __shared__ unsigned int hist[TK_BINS];
    __shared__ float buf[TK_CAP];
    __shared__ unsigned int csum[256];
    __shared__ unsigned int sh_bin, sh_less, sh_bincnt, sh_cnt;

    const int t = blockIdx.x;
    const int tid = threadIdx.x;
    const int lane = tid & 31;
    const float* srow = S + (size_t)t * VOCAB;

    const int shifts[3] = {20, 8, 0};
    const int nbins[3]  = {4096, 4096, 256};

    unsigned int P = 0;
    int lessTotal = 0;
    int level = 0;
    int gShift = 20;

    for (level = 0; level < 3; level++) {
        const int shift = shifts[level];
        const int bins = nbins[level];
        const unsigned int mask = bins - 1;
        const int prevShift = (level > 0) ? shifts[level - 1] : 32;

        for (int i = tid; i < bins; i += 256) hist[i] = 0;
        __syncthreads();

        for (int j = tid; j < VOCAB; j += 256) {
            unsigned int key = flip_key(srow[j]);
            bool match = (level == 0) || ((key >> prevShift) == P);
            int bin = match ? (int)((key >> shift) & mask) : -1;
            unsigned int grp = __match_any_sync(0xFFFFFFFFu, bin);
            int leader = __ffs(grp) - 1;
            if (lane == leader && bin >= 0)
                atomicAdd(&hist[bin], __popc(grp));
        }
        __syncthreads();

        // parallel scan: thread t owns chunk [t*cs, t*cs+cs)
        const int cs = bins >> 8;  // 16 or 1
        unsigned int mysum = 0;
        for (int b = 0; b < cs; b++) mysum += hist[tid * cs + b];
        csum[tid] = mysum;
        __syncthreads();
        // Kogge-Stone inclusive scan over 256
        #pragma unroll
        for (int off = 1; off < 256; off <<= 1) {
            unsigned int v = (tid >= off) ? csum[tid - off] : 0u;
            __syncthreads();
            csum[tid] += v;
            __syncthreads();
        }
        unsigned int incl = csum[tid];
        unsigned int excl = incl - mysum;
        const unsigned int R = (unsigned int)(KSEL - lessTotal);
        if (excl < R && R <= incl) {
            unsigned int cum = excl;
            for (int b = 0; b < cs; b++) {
                unsigned int c = hist[tid * cs + b];
                if (cum + c >= R) {
                    sh_bin = tid * cs + b;
                    sh_less = cum;
                    sh_bincnt = c;
                    break;
                }
                cum += c;
            }
        }
        __syncthreads();

        P = (level == 0) ? sh_bin : ((P << (prevShift - shift)) | sh_bin);
        lessTotal += (int)sh_less;
        gShift = shift;
        unsigned int cand = (unsigned int)lessTotal + sh_bincnt;
        __syncthreads();
        if (cand <= TK_CAP || level == 2) break;
    }

    // Gather candidates: (key >> gShift) <= P
    if (tid == 0) sh_cnt = 0;
    __syncthreads();
    for (int j = tid; j < VOCAB; j += 256) {
        float d = srow[j];
        unsigned int key = flip_key(d);
        if ((key >> gShift) <= P) {
            unsigned int p = atomicAdd(&sh_cnt, 1u);
            if (p < TK_CAP) buf[p] = d;
        }
    }
    __syncthreads();

    int n = (int)min(sh_cnt, (unsigned int)TK_CAP);
    int m = KSEL;
    while (m < n) m <<= 1;
    for (int i = n + tid; i < m; i += 256) buf[i] = __int_as_float(0x7F800000); // +inf
    __syncthreads();

    // bitonic sort ascending over m elements
    for (int ksz = 2; ksz <= m; ksz <<= 1) {
        for (int j2 = ksz >> 1; j2 > 0; j2 >>= 1) {
            for (int i = tid; i < m; i += 256) {
                int ixj = i ^ j2;
                if (ixj > i) {
                    float a = buf[i];
                    float b = buf[ixj];
                    bool up = ((i & ksz) == 0);
                    if ((a > b) == up) { buf[i] = b; buf[ixj] = a; }
                }
            }
            __syncthreads();
        }
    }

    if (tid < KSEL) out[(size_t)t * KSEL + tid] = buf[tid];
}

// ---------------------------------------------------------------------------
// Launch
// ---------------------------------------------------------------------------
extern "C" void kernel_launch(void* const* d_in, const int* in_sizes, int n_in,
                              void* d_out, int out_size) {
    const float* x = (const float*)d_in[0];   // [4096, 1024]
    const float* w = (const float*)d_in[1];   // [32000, 1024]
    float* out = (float*)d_out;               // [4096, 128]

    float *dist, *xsq, *bsq;
    __nv_bfloat16 *xb, *wb;
    cudaGetSymbolAddress((void**)&dist, g_dist);
    cudaGetSymbolAddress((void**)&xsq, g_xsq);
    cudaGetSymbolAddress((void**)&bsq, g_bsq);
    cudaGetSymbolAddress((void**)&xb, g_xb);
    cudaGetSymbolAddress((void**)&wb, g_wb);

    {
        size_t n4 = (size_t)TOKENS * DMODEL / 4;
        convert_bf16_kernel<<<(unsigned)((n4 + 255) / 256), 256>>>(x, xb, n4);
    }
    {
        size_t n4 = (size_t)VOCAB * DMODEL / 4;
        convert_bf16_kernel<<<(unsigned)((n4 + 255) / 256), 256>>>(w, wb, n4);
    }
    rowsq_kernel<<<TOKENS, 256>>>(x, xsq, DMODEL);
    rowsq_kernel<<<VOCAB, 256>>>(w, bsq, DMODEL);

    dim3 grid(TOKENS / BM, VOCAB / BN);  // (32, 250)
    gemm_dist_kernel<<<grid, 256>>>(xb, wb, xsq, bsq, dist);

    topk_kernel<<<TOKENS, 256>>>(dist, out);
}

// round 5
// speedup vs baseline: 3.4852x; 1.2753x over previous
#include <cuda_runtime.h>
#include <cuda_bf16.h>
#include <mma.h>
#include <cstdint>

#define TOKENS 4096
#define DMODEL 1024
#define VOCAB  32000
#define KSEL   128

// Does this compilation target support tcgen05 (arch-specific or family target)?
#if defined(__CUDA_ARCH_FEAT_SM103_ALL) || defined(__CUDA_ARCH_FEAT_SM100_ALL) || \
    defined(__CUDA_ARCH_FEAT_SM101_ALL) || defined(__CUDA_ARCH_SPECIFIC__) || \
    defined(__CUDA_ARCH_FAMILY_SPECIFIC__)
#define TC_PATH 1
#else
#define TC_PATH 0
#endif

// ---------------- GEMM tiling (both paths) ----------------
#define BM 128
#define BN 128

// tcgen05 path
#define BKT 64                    // K elems per smem tile (128 bytes bf16)
#define NKT (DMODEL / BKT)        // 16 k-tiles
#define STAGES 3
#define TILEB (128 * 128)         // 16KB per tile

#define SM_A      0
#define SM_B      (STAGES * TILEB)
#define SM_XS     (2 * STAGES * TILEB)             // 98304
#define SM_BS     (SM_XS + 512)
#define SM_TMEMP  (SM_BS + 512)
#define SM_MBAR   (SM_TMEMP + 16)
#define SM_TOTAL  (SM_MBAR + 64)

// Epilogue transpose stride: 132 floats => row starts 16B-aligned (132*4=528,
// 528 % 16 == 0), unlike 129 which trapped with misaligned LDS.128.
#define TSTRIDE 132

// wmma fallback path
#define FBK 32
#define FLDS (FBK + 8)            // 40

// idesc kind::f16: dtype F32(1<<4), atype BF16(1<<7), btype BF16(1<<10),
// N/8 << 17, M/16 << 24
#define MMA_IDESC ((1u<<4)|(1u<<7)|(1u<<10)|((BN/8u)<<17)|((BM/16u)<<24))

// Device scratch (no allocations allowed)
static __device__ float g_dist[(size_t)TOKENS * VOCAB];
static __device__ __nv_bfloat16 g_xb[(size_t)TOKENS * DMODEL];
static __device__ __nv_bfloat16 g_wb[(size_t)VOCAB * DMODEL];
static __device__ float g_xsq[TOKENS];
static __device__ float g_bsq[VOCAB];

// ---------------------------------------------------------------------------
// PTX helpers (generic)
// ---------------------------------------------------------------------------
__device__ __forceinline__ uint32_t smem_u32(const void* p) {
    uint32_t a;
    asm("{ .reg .u64 t; cvta.to.shared.u64 t, %1; cvt.u32.u64 %0, t; }" : "=r"(a) : "l"(p));
    return a;
}
__device__ __forceinline__ void cp_async16(uint32_t s, const void* g) {
    asm volatile("cp.async.cg.shared.global [%0], [%1], 16;\n" :: "r"(s), "l"(g));
}
__device__ __forceinline__ void cp_commit() { asm volatile("cp.async.commit_group;\n" ::); }
template <int N>
__device__ __forceinline__ void cp_wait() { asm volatile("cp.async.wait_group %0;\n" :: "n"(N)); }

#if TC_PATH
__device__ __forceinline__ bool elect_one() {
    uint32_t pred;
    asm volatile("{\n\t.reg .pred p;\n\telect.sync _|p, 0xFFFFFFFF;\n\t"
                 "selp.b32 %0, 1, 0, p;\n\t}" : "=r"(pred));
    return pred != 0;
}
__device__ __forceinline__ void mbar_init(uint32_t a, uint32_t cnt) {
    asm volatile("mbarrier.init.shared.b64 [%0], %1;" :: "r"(a), "r"(cnt) : "memory");
}
__device__ __forceinline__ void mbar_inval(uint32_t a) {
    asm volatile("mbarrier.inval.shared.b64 [%0];" :: "r"(a) : "memory");
}
__device__ __forceinline__ void mbar_wait(uint32_t a, uint32_t parity) {
    uint32_t done;
    asm volatile("{\n\t.reg .pred p;\n\t"
                 "mbarrier.try_wait.parity.acquire.cta.shared::cta.b64 p, [%1], %2;\n\t"
                 "selp.b32 %0, 1, 0, p;\n\t}"
                 : "=r"(done) : "r"(a), "r"(parity) : "memory");
    if (!done) {
        asm volatile("{\n\t.reg .pred P1;\n\t"
                     "WL_%=:\n\t"
                     "mbarrier.try_wait.parity.acquire.cta.shared::cta.b64 P1, [%0], %1, 0x989680;\n\t"
                     "@P1 bra.uni WD_%=;\n\t"
                     "bra.uni WL_%=;\n\t"
                     "WD_%=:\n\t}" :: "r"(a), "r"(parity) : "memory");
    }
}
__device__ __forceinline__ void tmem_alloc(uint32_t smem_res, uint32_t ncols) {
    asm volatile("tcgen05.alloc.cta_group::1.sync.aligned.shared::cta.b32 [%0], %1;"
                 :: "r"(smem_res), "r"(ncols) : "memory");
}
__device__ __forceinline__ void tmem_dealloc(uint32_t tmem, uint32_t ncols) {
    asm volatile("tcgen05.dealloc.cta_group::1.sync.aligned.b32 %0, %1;" :: "r"(tmem), "r"(ncols));
}
__device__ __forceinline__ void tmem_relinquish() {
    asm volatile("tcgen05.relinquish_alloc_permit.cta_group::1.sync.aligned;");
}
__device__ __forceinline__ void tc_commit(uint32_t mbar) {
    asm volatile("tcgen05.commit.cta_group::1.mbarrier::arrive::one.shared::cluster.b64 [%0];"
                 :: "r"(mbar) : "memory");
}
__device__ __forceinline__ void tc_fence_after() {
    asm volatile("tcgen05.fence::after_thread_sync;" ::: "memory");
}
__device__ __forceinline__ void tc_fence_before() {
    asm volatile("tcgen05.fence::before_thread_sync;" ::: "memory");
}
__device__ __forceinline__ void tc_wait_ld() {
    asm volatile("tcgen05.wait::ld.sync.aligned;" ::: "memory");
}
__device__ __forceinline__ void fence_async_shared() {
    asm volatile("fence.proxy.async.shared::cta;" ::: "memory");
}
__device__ __forceinline__ void mma_f16_ss(uint32_t d, uint64_t a, uint64_t b,
                                           uint32_t idesc, uint32_t en) {
    asm volatile("{\n\t.reg .pred p;\n\tsetp.ne.u32 p, %4, 0;\n\t"
                 "tcgen05.mma.cta_group::1.kind::f16 [%0], %1, %2, %3, {%5, %5, %5, %5}, p;\n\t}"
                 :: "r"(d), "l"(a), "l"(b), "r"(idesc), "r"(en), "r"(0u) : "memory");
}
__device__ __forceinline__ void ldtm_x32(uint32_t* r, uint32_t addr) {
    asm volatile("tcgen05.ld.sync.aligned.32x32b.x32.b32 "
                 "{%0, %1, %2, %3, %4, %5, %6, %7, "
                 " %8, %9, %10, %11, %12, %13, %14, %15, "
                 " %16, %17, %18, %19, %20, %21, %22, %23, "
                 " %24, %25, %26, %27, %28, %29, %30, %31}, [%32];"
                 : "=r"(r[0]), "=r"(r[1]), "=r"(r[2]), "=r"(r[3]),
                   "=r"(r[4]), "=r"(r[5]), "=r"(r[6]), "=r"(r[7]),
                   "=r"(r[8]), "=r"(r[9]), "=r"(r[10]), "=r"(r[11]),
                   "=r"(r[12]), "=r"(r[13]), "=r"(r[14]), "=r"(r[15]),
                   "=r"(r[16]), "=r"(r[17]), "=r"(r[18]), "=r"(r[19]),
                   "=r"(r[20]), "=r"(r[21]), "=r"(r[22]), "=r"(r[23]),
                   "=r"(r[24]), "=r"(r[25]), "=r"(r[26]), "=r"(r[27]),
                   "=r"(r[28]), "=r"(r[29]), "=r"(r[30]), "=r"(r[31])
                 : "r"(addr));
}
__device__ __forceinline__ uint64_t make_desc(uint32_t addr) {
    const uint64_t base = (uint64_t(2) << 61) | (uint64_t(1) << 46)
                        | (uint64_t(64) << 32) | (uint64_t(1) << 16);
    return base | ((uint64_t)(addr >> 4) & 0x3FFF);
}
#endif  // TC_PATH

__device__ __forceinline__ uint32_t sw128(uint32_t off) {
    return off ^ ((off >> 3) & 0x70);
}

// ---------------------------------------------------------------------------
// Fused fp32->bf16 convert + row squared-norm
// ---------------------------------------------------------------------------
__global__ void prep_kernel(const float* __restrict__ src,
                            __nv_bfloat16* __restrict__ dst,
                            float* __restrict__ sq) {
    __shared__ float warp_sums[8];
    const int row = blockIdx.x;
    const int tid = threadIdx.x;
    const float* s = src + (size_t)row * DMODEL;
    __nv_bfloat16* d = dst + (size_t)row * DMODEL;

    float acc = 0.f;
    int j = tid * 4;
    {
        float4 v = *(const float4*)&s[j];
        acc += v.x * v.x + v.y * v.y + v.z * v.z + v.w * v.w;
        __nv_bfloat162 lo = __floats2bfloat162_rn(v.x, v.y);
        __nv_bfloat162 hi = __floats2bfloat162_rn(v.z, v.w);
        uint2 p; p.x = *(uint32_t*)&lo; p.y = *(uint32_t*)&hi;
        *(uint2*)&d[j] = p;
    }
    #pragma unroll
    for (int off = 16; off > 0; off >>= 1)
        acc += __shfl_xor_sync(0xFFFFFFFFu, acc, off);
    if ((tid & 31) == 0) warp_sums[tid >> 5] = acc;
    __syncthreads();
    if (tid == 0) {
        float total = 0.f;
        #pragma unroll
        for (int w = 0; w < 8; w++) total += warp_sums[w];
        sq[row] = total;
    }
}

// ---------------------------------------------------------------------------
// GEMM + fused distance epilogue. dist = xsq + bsq - 2*dot.
// TC_PATH: tcgen05 SS MMA, 3-stage cp.async pipeline.
// else:    bf16 WMMA (round-2 proven fallback).
// ---------------------------------------------------------------------------
__global__ void __launch_bounds__(256)
gemm_dist_tc_kernel(const __nv_bfloat16* __restrict__ A,
                    const __nv_bfloat16* __restrict__ B,
                    const float* __restrict__ xsq,
                    const float* __restrict__ bsq,
                    float* __restrict__ C) {
    extern __shared__ __align__(1024) char sm[];
    const int tid = threadIdx.x;
    const int warp = tid >> 5;
    const int row0 = blockIdx.x * BM;
    const int col0 = blockIdx.y * BN;

#if TC_PATH
    const uint32_t smem_base = smem_u32(sm);
    float* xs_s = (float*)(sm + SM_XS);
    float* bs_s = (float*)(sm + SM_BS);
    const uint32_t mbar = smem_base + SM_MBAR;

    if (warp == 0) tmem_alloc(smem_base + SM_TMEMP, 128);
    if (tid == 0) mbar_init(mbar, 1);
    if (tid < BM) xs_s[tid] = xsq[row0 + tid];
    else if (tid >= 128 && tid < 128 + BN) bs_s[tid - 128] = bsq[col0 + tid - 128];
    __syncthreads();
    uint32_t tmem;
    asm volatile("ld.shared.b32 %0, [%1];" : "=r"(tmem) : "r"(smem_base + SM_TMEMP));

    auto load_tile = [&](int kt) {
        const int stage = kt % STAGES;
        const int k0 = kt * BKT;
        const uint32_t abase = smem_base + SM_A + stage * TILEB;
        const uint32_t bbase = smem_base + SM_B + stage * TILEB;
        #pragma unroll
        for (int i = 0; i < 4; i++) {
            int chunk = tid + i * 256;
            int r = chunk >> 3;
            int cb = (chunk & 7) * 16;
            uint32_t sw = sw128((uint32_t)(r * 128 + cb));
            cp_async16(abase + sw, A + (size_t)(row0 + r) * DMODEL + k0 + (chunk & 7) * 8);
            cp_async16(bbase + sw, B + (size_t)(col0 + r) * DMODEL + k0 + (chunk & 7) * 8);
        }
        cp_commit();
    };

    load_tile(0);
    load_tile(1);

    for (int kt = 0; kt < NKT; kt++) {
        if (kt >= 1) mbar_wait(mbar, (kt - 1) & 1);
        if (kt + 2 < NKT) load_tile(kt + 2);
        if (kt + 2 < NKT) cp_wait<2>();
        else if (kt + 1 < NKT) cp_wait<1>();
        else cp_wait<0>();
        fence_async_shared();
        __syncthreads();

        if (warp == 0 && elect_one()) {
            const int stage = kt % STAGES;
            uint64_t ad = make_desc(smem_base + SM_A + stage * TILEB);
            uint64_t bd = make_desc(smem_base + SM_B + stage * TILEB);
            #pragma unroll
            for (int k = 0; k < 4; k++) {
                uint32_t en = (kt > 0 || k > 0) ? 1u : 0u;
                mma_f16_ss(tmem, ad + k * 2, bd + k * 2, MMA_IDESC, en);
            }
            tc_commit(mbar);
        }
    }

    mbar_wait(mbar, (NKT - 1) & 1);
    tc_fence_after();
    __syncthreads();

    float* T = (float*)sm;  // 128 x TSTRIDE fp32 transpose buffer (67.6KB)
    if (tid < 128) {
        float base = xs_s[tid];
        #pragma unroll
        for (int cb = 0; cb < 128; cb += 32) {
            uint32_t regs[32];
            ldtm_x32(regs, tmem + cb);
            tc_wait_ld();
            #pragma unroll
            for (int j = 0; j < 32; j++) {
                float dot = __uint_as_float(regs[j]);
                T[tid * TSTRIDE + cb + j] = fmaf(-2.0f, dot, base + bs_s[cb + j]);
            }
        }
        tc_fence_before();
    }
    __syncthreads();

    {
        int r = tid >> 1;
        int c0 = (tid & 1) * 64;
        float* dst = &C[(size_t)(row0 + r) * VOCAB + col0 + c0];
        const float* srcT = &T[r * TSTRIDE + c0];
        #pragma unroll
        for (int j = 0; j < 16; j++) {
            float4 v = *(const float4*)&srcT[j * 4];
            *(float4*)&dst[j * 4] = v;
        }
    }

    __syncthreads();
    if (tid == 0) mbar_inval(mbar);
    if (warp == 0) {
        tmem_relinquish();
        tmem_dealloc(tmem, 128);
    }

#else  // ---------------- WMMA fallback (round-2) ----------------
    using namespace nvcuda;
    __nv_bfloat16* AsBase = (__nv_bfloat16*)sm;
    __nv_bfloat16* BsBase = (__nv_bfloat16*)(sm + 2 * BM * FLDS * 2);
    float* xs_s = (float*)(sm + 4 * BM * FLDS * 2);
    float* bs_s = xs_s + BM;
    float* stg = (float*)sm;

    const int lane = tid & 31;
    const int wm = warp & 1;
    const int wn = warp >> 1;

    if (tid < BM) xs_s[tid] = xsq[row0 + tid];
    if (tid < BN) bs_s[tid] = bsq[col0 + tid];

    wmma::fragment<wmma::accumulator, 16, 16, 16, float> acc[4][2];
    #pragma unroll
    for (int i = 0; i < 4; i++)
        #pragma unroll
        for (int j = 0; j < 2; j++)
            wmma::fill_fragment(acc[i][j], 0.0f);

    auto asPtr = [&](int stage, int r, int c) -> __nv_bfloat16* {
        return AsBase + (size_t)stage * BM * FLDS + r * FLDS + c;
    };
    auto bsPtr = [&](int stage, int r, int c) -> __nv_bfloat16* {
        return BsBase + (size_t)stage * BN * FLDS + r * FLDS + c;
    };
    auto issue_loads = [&](int stage, int k0) {
        #pragma unroll
        for (int i = 0; i < 2; i++) {
            int c = tid + i * 256;
            int r = c >> 2;
            int cc = (c & 3) * 8;
            cp_async16(smem_u32(asPtr(stage, r, cc)),
                       A + (size_t)(row0 + r) * DMODEL + k0 + cc);
        }
        #pragma unroll
        for (int i = 0; i < 2; i++) {
            int c = tid + i * 256;
            int r = c >> 2;
            int cc = (c & 3) * 8;
            cp_async16(smem_u32(bsPtr(stage, r, cc)),
                       B + (size_t)(col0 + r) * DMODEL + k0 + cc);
        }
        cp_commit();
    };

    issue_loads(0, 0);
    const int NTF = DMODEL / FBK;
    for (int kt = 0; kt < NTF; kt++) {
        int stage = kt & 1;
        if (kt + 1 < NTF) { issue_loads((kt + 1) & 1, (kt + 1) * FBK); cp_wait<1>(); }
        else cp_wait<0>();
        __syncthreads();

        #pragma unroll
        for (int kk = 0; kk < FBK; kk += 16) {
            wmma::fragment<wmma::matrix_a, 16, 16, 16, __nv_bfloat16, wmma::row_major> af[4];
            wmma::fragment<wmma::matrix_b, 16, 16, 16, __nv_bfloat16, wmma::col_major> bf[2];
            #pragma unroll
            for (int mi = 0; mi < 4; mi++)
                wmma::load_matrix_sync(af[mi], asPtr(stage, wm * 64 + mi * 16, kk), FLDS);
            #pragma unroll
            for (int ni = 0; ni < 2; ni++)
                wmma::load_matrix_sync(bf[ni], bsPtr(stage, wn * 32 + ni * 16, kk), FLDS);
            #pragma unroll
            for (int mi = 0; mi < 4; mi++)
                #pragma unroll
                for (int ni = 0; ni < 2; ni++)
                    wmma::mma_sync(acc[mi][ni], af[mi], bf[ni], acc[mi][ni]);
        }
        __syncthreads();
    }

    float* mystg = stg + warp * 16 * 20;
    #pragma unroll
    for (int mi = 0; mi < 4; mi++) {
        #pragma unroll
        for (int ni = 0; ni < 2; ni++) {
            wmma::store_matrix_sync(mystg, acc[mi][ni], 20, wmma::mem_row_major);
            __syncwarp();
            int r = lane >> 1;
            int cb = (lane & 1) * 8;
            int grow = wm * 64 + mi * 16 + r;
            int gcol = wn * 32 + ni * 16 + cb;
            float base = xs_s[grow];
            float4 o0, o1;
            #pragma unroll
            for (int c = 0; c < 8; c++) {
                float dot = mystg[r * 20 + cb + c];
                ((c < 4) ? ((float*)&o0)[c] : ((float*)&o1)[c - 4]) =
                    fmaf(-2.0f, dot, base + bs_s[gcol + c]);
            }
            float* dst = &C[(size_t)(row0 + grow) * VOCAB + col0 + gcol];
            *(float4*)dst = o0;
            *(float4*)(dst + 4) = o1;
            __syncwarp();
        }
    }
#endif
}

// ---------------------------------------------------------------------------
// Top-128-smallest per row (histogram + gather + bitonic sort)
// ---------------------------------------------------------------------------
__device__ __forceinline__ unsigned int flip_key(float f) {
    unsigned int u = __float_as_uint(f);
    return u ^ ((u & 0x80000000u) ? 0xFFFFFFFFu : 0x80000000u);
}

#define TK_BINS 4096
#define TK_CAP  4096

__global__ void __launch_bounds__(256) topk_kernel(
    const float* __restrict__ S, float* __restrict__ out) {
    __shared__ unsigned int hist[TK_BINS];
    __shared__ float buf[TK_CAP];
    __shared__ unsigned int csum[256];
    __shared__ unsigned int sh_bin, sh_less, sh_bincnt, sh_cnt;

    const int t = blockIdx.x;
    const int tid = threadIdx.x;
    const int lane = tid & 31;
    const float* srow = S + (size_t)t * VOCAB;

    const int shifts[3] = {20, 8, 0};
    const int nbins[3]  = {4096, 4096, 256};

    unsigned int P = 0;
    int lessTotal = 0;
    int gShift = 20;

    for (int level = 0; level < 3; level++) {
        const int shift = shifts[level];
        const int bins = nbins[level];
        const unsigned int mask = bins - 1;
        const int prevShift = (level > 0) ? shifts[level - 1] : 32;

        for (int i = tid; i < bins; i += 256) hist[i] = 0;
        __syncthreads();

        for (int j = tid; j < VOCAB; j += 256) {
            unsigned int key = flip_key(srow[j]);
            bool match = (level == 0) || ((key >> prevShift) == P);
            int bin = match ? (int)((key >> shift) & mask) : -1;
            unsigned int grp = __match_any_sync(0xFFFFFFFFu, bin);
            int leader = __ffs(grp) - 1;
            if (lane == leader && bin >= 0)
                atomicAdd(&hist[bin], __popc(grp));
        }
        __syncthreads();

        const int cs = bins >> 8;
        unsigned int mysum = 0;
        for (int b = 0; b < cs; b++) mysum += hist[tid * cs + b];
        csum[tid] = mysum;
        __syncthreads();
        #pragma unroll
        for (int off = 1; off < 256; off <<= 1) {
            unsigned int v = (tid >= off) ? csum[tid - off] : 0u;
            __syncthreads();
            csum[tid] += v;
            __syncthreads();
        }
        unsigned int incl = csum[tid];
        unsigned int excl = incl - mysum;
        const unsigned int R = (unsigned int)(KSEL - lessTotal);
        if (excl < R && R <= incl) {
            unsigned int cum = excl;
            for (int b = 0; b < cs; b++) {
                unsigned int c = hist[tid * cs + b];
                if (cum + c >= R) {
                    sh_bin = tid * cs + b;
                    sh_less = cum;
                    sh_bincnt = c;
                    break;
                }
                cum += c;
            }
        }
        __syncthreads();

        P = (level == 0) ? sh_bin : ((P << (prevShift - shift)) | sh_bin);
        lessTotal += (int)sh_less;
        gShift = shift;
        unsigned int cand = (unsigned int)lessTotal + sh_bincnt;
        __syncthreads();
        if (cand <= TK_CAP || level == 2) break;
    }

    if (tid == 0) sh_cnt = 0;
    __syncthreads();
    for (int j = tid; j < VOCAB; j += 256) {
        float d = srow[j];
        unsigned int key = flip_key(d);
        if ((key >> gShift) <= P) {
            unsigned int p = atomicAdd(&sh_cnt, 1u);
            if (p < TK_CAP) buf[p] = d;
        }
    }
    __syncthreads();

    int n = (int)min(sh_cnt, (unsigned int)TK_CAP);
    int m = KSEL;
    while (m < n) m <<= 1;
    for (int i = n + tid; i < m; i += 256) buf[i] = __int_as_float(0x7F800000);
    __syncthreads();

    for (int ksz = 2; ksz <= m; ksz <<= 1) {
        for (int j2 = ksz >> 1; j2 > 0; j2 >>= 1) {
            for (int i = tid; i < m; i += 256) {
                int ixj = i ^ j2;
                if (ixj > i) {
                    float a = buf[i];
                    float b = buf[ixj];
                    bool up = ((i & ksz) == 0);
                    if ((a > b) == up) { buf[i] = b; buf[ixj] = a; }
                }
            }
            __syncthreads();
        }
    }

    if (tid < KSEL) out[(size_t)t * KSEL + tid] = buf[tid];
}

// ---------------------------------------------------------------------------
// Launch
// ---------------------------------------------------------------------------
extern "C" void kernel_launch(void* const* d_in, const int* in_sizes, int n_in,
                              void* d_out, int out_size) {
    const float* x = (const float*)d_in[0];   // [4096, 1024]
    const float* w = (const float*)d_in[1];   // [32000, 1024]
    float* out = (float*)d_out;               // [4096, 128]

    float *dist, *xsq, *bsq;
    __nv_bfloat16 *xb, *wb;
    cudaGetSymbolAddress((void**)&dist, g_dist);
    cudaGetSymbolAddress((void**)&xsq, g_xsq);
    cudaGetSymbolAddress((void**)&bsq, g_bsq);
    cudaGetSymbolAddress((void**)&xb, g_xb);
    cudaGetSymbolAddress((void**)&wb, g_wb);

    prep_kernel<<<TOKENS, 256>>>(x, xb, xsq);
    prep_kernel<<<VOCAB, 256>>>(w, wb, bsq);

    cudaFuncSetAttribute(gemm_dist_tc_kernel,
                         cudaFuncAttributeMaxDynamicSharedMemorySize, SM_TOTAL);
    dim3 grid(TOKENS / BM, VOCAB / BN);  // (32, 250)
    gemm_dist_tc_kernel<<<grid, 256, SM_TOTAL>>>(xb, wb, xsq, bsq, dist);

    topk_kernel<<<TOKENS, 256>>>(dist, out);
}

// round 6
// speedup vs baseline: 5.0029x; 1.4355x over previous
#include <cuda_runtime.h>
#include <cuda_bf16.h>
#include <mma.h>
#include <cstdint>

#define TOKENS 4096
#define DMODEL 1024
#define VOCAB  32000
#define KSEL   128

#if defined(__CUDA_ARCH_FEAT_SM103_ALL) || defined(__CUDA_ARCH_FEAT_SM100_ALL) || \
    defined(__CUDA_ARCH_FEAT_SM101_ALL) || defined(__CUDA_ARCH_SPECIFIC__) || \
    defined(__CUDA_ARCH_FAMILY_SPECIFIC__)
#define TC_PATH 1
#else
#define TC_PATH 0
#endif

// ---------------- GEMM tiling ----------------
#define BM 128
#define BN 128
#define BKT 64                    // K elems per smem tile (128B rows)
#define NKT (DMODEL / BKT)        // 16 k-tiles
#define STAGES 3
#define TILEB (128 * 128)         // 16KB per tile buffer

#define SM_A      0
#define SM_B      (STAGES * TILEB)
#define SM_XS     (2 * STAGES * TILEB)             // 98304
#define SM_BS     (SM_XS + 512)
#define SM_TMEMP  (SM_BS + 512)
#define SM_MBAR   (SM_TMEMP + 16)                  // free[3] @0,8,16 full[3] @24,32,40 done @48
#define SM_TOTAL  (SM_MBAR + 64)

#define TSTRIDE 132               // epilogue transpose stride (16B-aligned rows)

// wmma fallback path
#define FBK 32
#define FLDS (FBK + 8)

#define MMA_IDESC ((1u<<4)|(1u<<7)|(1u<<10)|((BN/8u)<<17)|((BM/16u)<<24))

// Device scratch
static __device__ float g_dist[(size_t)TOKENS * VOCAB];
static __device__ __nv_bfloat16 g_xb[(size_t)TOKENS * DMODEL];
static __device__ __nv_bfloat16 g_wb[(size_t)VOCAB * DMODEL];
static __device__ float g_xsq[TOKENS];
static __device__ float g_bsq[VOCAB];

// ---------------------------------------------------------------------------
// PTX helpers
// ---------------------------------------------------------------------------
__device__ __forceinline__ uint32_t smem_u32(const void* p) {
    uint32_t a;
    asm("{ .reg .u64 t; cvta.to.shared.u64 t, %1; cvt.u32.u64 %0, t; }" : "=r"(a) : "l"(p));
    return a;
}
__device__ __forceinline__ void cp_async16(uint32_t s, const void* g) {
    asm volatile("cp.async.cg.shared.global [%0], [%1], 16;\n" :: "r"(s), "l"(g));
}
__device__ __forceinline__ void cp_commit() { asm volatile("cp.async.commit_group;\n" ::); }
template <int N>
__device__ __forceinline__ void cp_wait() { asm volatile("cp.async.wait_group %0;\n" :: "n"(N)); }

#if TC_PATH
__device__ __forceinline__ bool elect_one() {
    uint32_t pred;
    asm volatile("{\n\t.reg .pred p;\n\telect.sync _|p, 0xFFFFFFFF;\n\t"
                 "selp.b32 %0, 1, 0, p;\n\t}" : "=r"(pred));
    return pred != 0;
}
__device__ __forceinline__ void mbar_init(uint32_t a, uint32_t cnt) {
    asm volatile("mbarrier.init.shared.b64 [%0], %1;" :: "r"(a), "r"(cnt) : "memory");
}
__device__ __forceinline__ void mbar_inval(uint32_t a) {
    asm volatile("mbarrier.inval.shared.b64 [%0];" :: "r"(a) : "memory");
}
__device__ __forceinline__ void mbar_wait(uint32_t a, uint32_t parity) {
    uint32_t done;
    asm volatile("{\n\t.reg .pred p;\n\t"
                 "mbarrier.try_wait.parity.acquire.cta.shared::cta.b64 p, [%1], %2;\n\t"
                 "selp.b32 %0, 1, 0, p;\n\t}"
                 : "=r"(done) : "r"(a), "r"(parity) : "memory");
    if (!done) {
        asm volatile("{\n\t.reg .pred P1;\n\t"
                     "WL_%=:\n\t"
                     "mbarrier.try_wait.parity.acquire.cta.shared::cta.b64 P1, [%0], %1, 0x989680;\n\t"
                     "@P1 bra.uni WD_%=;\n\t"
                     "bra.uni WL_%=;\n\t"
                     "WD_%=:\n\t}" :: "r"(a), "r"(parity) : "memory");
    }
}
__device__ __forceinline__ void cp_async_mbar_arrive(uint32_t mbar) {
    asm volatile("cp.async.mbarrier.arrive.noinc.shared::cta.b64 [%0];" :: "r"(mbar) : "memory");
}
__device__ __forceinline__ void tmem_alloc(uint32_t smem_res, uint32_t ncols) {
    asm volatile("tcgen05.alloc.cta_group::1.sync.aligned.shared::cta.b32 [%0], %1;"
                 :: "r"(smem_res), "r"(ncols) : "memory");
}
__device__ __forceinline__ void tmem_dealloc(uint32_t tmem, uint32_t ncols) {
    asm volatile("tcgen05.dealloc.cta_group::1.sync.aligned.b32 %0, %1;" :: "r"(tmem), "r"(ncols));
}
__device__ __forceinline__ void tmem_relinquish() {
    asm volatile("tcgen05.relinquish_alloc_permit.cta_group::1.sync.aligned;");
}
__device__ __forceinline__ void tc_commit(uint32_t mbar) {
    asm volatile("tcgen05.commit.cta_group::1.mbarrier::arrive::one.shared::cluster.b64 [%0];"
                 :: "r"(mbar) : "memory");
}
__device__ __forceinline__ void tc_fence_after() {
    asm volatile("tcgen05.fence::after_thread_sync;" ::: "memory");
}
__device__ __forceinline__ void tc_fence_before() {
    asm volatile("tcgen05.fence::before_thread_sync;" ::: "memory");
}
__device__ __forceinline__ void tc_wait_ld() {
    asm volatile("tcgen05.wait::ld.sync.aligned;" ::: "memory");
}
__device__ __forceinline__ void fence_async_shared() {
    asm volatile("fence.proxy.async.shared::cta;" ::: "memory");
}
__device__ __forceinline__ void mma_f16_ss(uint32_t d, uint64_t a, uint64_t b,
                                           uint32_t idesc, uint32_t en) {
    asm volatile("{\n\t.reg .pred p;\n\tsetp.ne.u32 p, %4, 0;\n\t"
                 "tcgen05.mma.cta_group::1.kind::f16 [%0], %1, %2, %3, {%5, %5, %5, %5}, p;\n\t}"
                 :: "r"(d), "l"(a), "l"(b), "r"(idesc), "r"(en), "r"(0u) : "memory");
}
__device__ __forceinline__ void ldtm_x32(uint32_t* r, uint32_t addr) {
    asm volatile("tcgen05.ld.sync.aligned.32x32b.x32.b32 "
                 "{%0, %1, %2, %3, %4, %5, %6, %7, "
                 " %8, %9, %10, %11, %12, %13, %14, %15, "
                 " %16, %17, %18, %19, %20, %21, %22, %23, "
                 " %24, %25, %26, %27, %28, %29, %30, %31}, [%32];"
                 : "=r"(r[0]), "=r"(r[1]), "=r"(r[2]), "=r"(r[3]),
                   "=r"(r[4]), "=r"(r[5]), "=r"(r[6]), "=r"(r[7]),
                   "=r"(r[8]), "=r"(r[9]), "=r"(r[10]), "=r"(r[11]),
                   "=r"(r[12]), "=r"(r[13]), "=r"(r[14]), "=r"(r[15]),
                   "=r"(r[16]), "=r"(r[17]), "=r"(r[18]), "=r"(r[19]),
                   "=r"(r[20]), "=r"(r[21]), "=r"(r[22]), "=r"(r[23]),
                   "=r"(r[24]), "=r"(r[25]), "=r"(r[26]), "=r"(r[27]),
                   "=r"(r[28]), "=r"(r[29]), "=r"(r[30]), "=r"(r[31])
                 : "r"(addr));
}
__device__ __forceinline__ uint64_t make_desc(uint32_t addr) {
    const uint64_t base = (uint64_t(2) << 61) | (uint64_t(1) << 46)
                        | (uint64_t(64) << 32) | (uint64_t(1) << 16);
    return base | ((uint64_t)(addr >> 4) & 0x3FFF);
}
#endif  // TC_PATH

__device__ __forceinline__ uint32_t sw128(uint32_t off) {
    return off ^ ((off >> 3) & 0x70);
}

// ---------------------------------------------------------------------------
// Fused fp32->bf16 convert + row squared-norm
// ---------------------------------------------------------------------------
__global__ void prep_kernel(const float* __restrict__ src,
                            __nv_bfloat16* __restrict__ dst,
                            float* __restrict__ sq) {
    __shared__ float warp_sums[8];
    const int row = blockIdx.x;
    const int tid = threadIdx.x;
    const float* s = src + (size_t)row * DMODEL;
    __nv_bfloat16* d = dst + (size_t)row * DMODEL;

    float acc = 0.f;
    int j = tid * 4;
    {
        float4 v = *(const float4*)&s[j];
        acc += v.x * v.x + v.y * v.y + v.z * v.z + v.w * v.w;
        __nv_bfloat162 lo = __floats2bfloat162_rn(v.x, v.y);
        __nv_bfloat162 hi = __floats2bfloat162_rn(v.z, v.w);
        uint2 p; p.x = *(uint32_t*)&lo; p.y = *(uint32_t*)&hi;
        *(uint2*)&d[j] = p;
    }
    #pragma unroll
    for (int off = 16; off > 0; off >>= 1)
        acc += __shfl_xor_sync(0xFFFFFFFFu, acc, off);
    if ((tid & 31) == 0) warp_sums[tid >> 5] = acc;
    __syncthreads();
    if (tid == 0) {
        float total = 0.f;
        #pragma unroll
        for (int w = 0; w < 8; w++) total += warp_sums[w];
        sq[row] = total;
    }
}

// ---------------------------------------------------------------------------
// GEMM + fused distance epilogue. dist = xsq + bsq - 2*dot.
// TC_PATH: warp-specialized mbarrier pipeline (warp0=MMA, warps1-7=producers).
// ---------------------------------------------------------------------------
__global__ void __launch_bounds__(256)
gemm_dist_tc_kernel(const __nv_bfloat16* __restrict__ A,
                    const __nv_bfloat16* __restrict__ B,
                    const float* __restrict__ xsq,
                    const float* __restrict__ bsq,
                    float* __restrict__ C) {
    extern __shared__ __align__(1024) char sm[];
    const int tid = threadIdx.x;
    const int warp = tid >> 5;
    const int row0 = blockIdx.x * BM;
    const int col0 = blockIdx.y * BN;

#if TC_PATH
    const uint32_t smem_base = smem_u32(sm);
    float* xs_s = (float*)(sm + SM_XS);
    float* bs_s = (float*)(sm + SM_BS);
    const uint32_t mb_free0 = smem_base + SM_MBAR;        // +s*8
    const uint32_t mb_full0 = smem_base + SM_MBAR + 24;   // +s*8
    const uint32_t mb_done  = smem_base + SM_MBAR + 48;

    if (warp == 0) tmem_alloc(smem_base + SM_TMEMP, 128);
    if (tid == 0) {
        #pragma unroll
        for (int s = 0; s < STAGES; s++) {
            mbar_init(mb_free0 + s * 8, 1);     // armed by MMA commit
            mbar_init(mb_full0 + s * 8, 224);   // armed by producer cp.async arrives
        }
        mbar_init(mb_done, 1);
    }
    if (tid < BM) xs_s[tid] = xsq[row0 + tid];
    else if (tid >= 128 && tid < 128 + BN) bs_s[tid - 128] = bsq[col0 + tid - 128];
    __syncthreads();
    uint32_t tmem;
    asm volatile("ld.shared.b32 %0, [%1];" : "=r"(tmem) : "r"(smem_base + SM_TMEMP));

    if (warp == 0) {
        // ------- consumer: MMA warp -------
        for (int kt = 0; kt < NKT; kt++) {
            const int s = kt % STAGES;
            const int w = kt / STAGES;
            mbar_wait(mb_full0 + s * 8, w & 1);
            fence_async_shared();
            if (elect_one()) {
                uint64_t ad = make_desc(smem_base + SM_A + s * TILEB);
                uint64_t bd = make_desc(smem_base + SM_B + s * TILEB);
                #pragma unroll
                for (int k = 0; k < 4; k++) {
                    uint32_t en = (kt > 0 || k > 0) ? 1u : 0u;
                    mma_f16_ss(tmem, ad + k * 2, bd + k * 2, MMA_IDESC, en);
                }
                tc_commit((kt == NKT - 1) ? mb_done : (mb_free0 + s * 8));
            }
        }
    } else {
        // ------- producers: warps 1-7 (224 threads) -------
        const int ptid = tid - 32;
        for (int kt = 0; kt < NKT; kt++) {
            const int s = kt % STAGES;
            const int w = kt / STAGES;
            mbar_wait(mb_free0 + s * 8, (w & 1) ^ 1);   // fresh-mbar parity-1 passes
            const int k0 = kt * BKT;
            const uint32_t abase = smem_base + SM_A + s * TILEB;
            const uint32_t bbase = smem_base + SM_B + s * TILEB;
            // 2048 chunks of 16B: [0,1024) = A, [1024,2048) = B
            for (int c = ptid; c < 2048; c += 224) {
                int half = c >> 10;
                int cc = c & 1023;
                int r = cc >> 3;
                int o8 = cc & 7;
                uint32_t sw = sw128((uint32_t)(r * 128 + o8 * 16));
                if (half == 0)
                    cp_async16(abase + sw, A + (size_t)(row0 + r) * DMODEL + k0 + o8 * 8);
                else
                    cp_async16(bbase + sw, B + (size_t)(col0 + r) * DMODEL + k0 + o8 * 8);
            }
            cp_async_mbar_arrive(mb_full0 + s * 8);
        }
    }

    // ------- epilogue: everyone waits final MMA completion -------
    mbar_wait(mb_done, 0);
    tc_fence_after();

    float* T = (float*)sm;  // 128 x TSTRIDE fp32 (67.6KB, aliases stage buffers)
    if (tid < 128) {
        float base = xs_s[tid];
        #pragma unroll
        for (int cb = 0; cb < 128; cb += 32) {
            uint32_t regs[32];
            ldtm_x32(regs, tmem + cb);
            tc_wait_ld();
            #pragma unroll
            for (int j = 0; j < 32; j++) {
                float dot = __uint_as_float(regs[j]);
                T[tid * TSTRIDE + cb + j] = fmaf(-2.0f, dot, base + bs_s[cb + j]);
            }
        }
        tc_fence_before();
    }
    __syncthreads();

    {
        int r = tid >> 1;
        int c0 = (tid & 1) * 64;
        float* dst = &C[(size_t)(row0 + r) * VOCAB + col0 + c0];
        const float* srcT = &T[r * TSTRIDE + c0];
        #pragma unroll
        for (int j = 0; j < 16; j++) {
            float4 v = *(const float4*)&srcT[j * 4];
            *(float4*)&dst[j * 4] = v;
        }
    }

    __syncthreads();
    if (tid == 0) {
        #pragma unroll
        for (int s = 0; s < STAGES; s++) {
            mbar_inval(mb_free0 + s * 8);
            mbar_inval(mb_full0 + s * 8);
        }
        mbar_inval(mb_done);
    }
    __syncthreads();
    if (warp == 0) {
        tmem_relinquish();
        tmem_dealloc(tmem, 128);
    }

#else  // ---------------- WMMA fallback ----------------
    using namespace nvcuda;
    __nv_bfloat16* AsBase = (__nv_bfloat16*)sm;
    __nv_bfloat16* BsBase = (__nv_bfloat16*)(sm + 2 * BM * FLDS * 2);
    float* xs_s = (float*)(sm + 4 * BM * FLDS * 2);
    float* bs_s = xs_s + BM;
    float* stg = (float*)sm;

    const int lane = tid & 31;
    const int wm = warp & 1;
    const int wn = warp >> 1;

    if (tid < BM) xs_s[tid] = xsq[row0 + tid];
    if (tid < BN) bs_s[tid] = bsq[col0 + tid];

    wmma::fragment<wmma::accumulator, 16, 16, 16, float> acc[4][2];
    #pragma unroll
    for (int i = 0; i < 4; i++)
        #pragma unroll
        for (int j = 0; j < 2; j++)
            wmma::fill_fragment(acc[i][j], 0.0f);

    auto asPtr = [&](int stage, int r, int c) -> __nv_bfloat16* {
        return AsBase + (size_t)stage * BM * FLDS + r * FLDS + c;
    };
    auto bsPtr = [&](int stage, int r, int c) -> __nv_bfloat16* {
        return BsBase + (size_t)stage * BN * FLDS + r * FLDS + c;
    };
    auto issue_loads = [&](int stage, int k0) {
        #pragma unroll
        for (int i = 0; i < 2; i++) {
            int c = tid + i * 256;
            int r = c >> 2;
            int cc = (c & 3) * 8;
            cp_async16(smem_u32(asPtr(stage, r, cc)),
                       A + (size_t)(row0 + r) * DMODEL + k0 + cc);
        }
        #pragma unroll
        for (int i = 0; i < 2; i++) {
            int c = tid + i * 256;
            int r = c >> 2;
            int cc = (c & 3) * 8;
            cp_async16(smem_u32(bsPtr(stage, r, cc)),
                       B + (size_t)(col0 + r) * DMODEL + k0 + cc);
        }
        cp_commit();
    };

    issue_loads(0, 0);
    const int NTF = DMODEL / FBK;
    for (int kt = 0; kt < NTF; kt++) {
        int stage = kt & 1;
        if (kt + 1 < NTF) { issue_loads((kt + 1) & 1, (kt + 1) * FBK); cp_wait<1>(); }
        else cp_wait<0>();
        __syncthreads();

        #pragma unroll
        for (int kk = 0; kk < FBK; kk += 16) {
            wmma::fragment<wmma::matrix_a, 16, 16, 16, __nv_bfloat16, wmma::row_major> af[4];
            wmma::fragment<wmma::matrix_b, 16, 16, 16, __nv_bfloat16, wmma::col_major> bf[2];
            #pragma unroll
            for (int mi = 0; mi < 4; mi++)
                wmma::load_matrix_sync(af[mi], asPtr(stage, wm * 64 + mi * 16, kk), FLDS);
            #pragma unroll
            for (int ni = 0; ni < 2; ni++)
                wmma::load_matrix_sync(bf[ni], bsPtr(stage, wn * 32 + ni * 16, kk), FLDS);
            #pragma unroll
            for (int mi = 0; mi < 4; mi++)
                #pragma unroll
                for (int ni = 0; ni < 2; ni++)
                    wmma::mma_sync(acc[mi][ni], af[mi], bf[ni], acc[mi][ni]);
        }
        __syncthreads();
    }

    float* mystg = stg + warp * 16 * 20;
    #pragma unroll
    for (int mi = 0; mi < 4; mi++) {
        #pragma unroll
        for (int ni = 0; ni < 2; ni++) {
            wmma::store_matrix_sync(mystg, acc[mi][ni], 20, wmma::mem_row_major);
            __syncwarp();
            int r = lane >> 1;
            int cb = (lane & 1) * 8;
            int grow = wm * 64 + mi * 16 + r;
            int gcol = wn * 32 + ni * 16 + cb;
            float base = xs_s[grow];
            float4 o0, o1;
            #pragma unroll
            for (int c = 0; c < 8; c++) {
                float dot = mystg[r * 20 + cb + c];
                ((c < 4) ? ((float*)&o0)[c] : ((float*)&o1)[c - 4]) =
                    fmaf(-2.0f, dot, base + bs_s[gcol + c]);
            }
            float* dst = &C[(size_t)(row0 + grow) * VOCAB + col0 + gcol];
            *(float4*)dst = o0;
            *(float4*)(dst + 4) = o1;
            __syncwarp();
        }
    }
#endif
}

// ---------------------------------------------------------------------------
// Top-128-smallest per row: sample-select (one gather pass), with exact
// radix-select as a terminal fallback for pathological distributions.
// ---------------------------------------------------------------------------
__device__ __forceinline__ unsigned int flip_key(float f) {
    unsigned int u = __float_as_uint(f);
    return u ^ ((u & 0x80000000u) ? 0xFFFFFFFFu : 0x80000000u);
}

#define TK_CAP 4096

__global__ void __launch_bounds__(256) topk_kernel(
    const float* __restrict__ S, float* __restrict__ out) {
    __shared__ uint32_t scratch[TK_CAP];   // radix hist / candidate buffer (alias)
    __shared__ float samp[256];
    __shared__ uint32_t csum[256];
    __shared__ uint32_t sh_cnt, sh_bin, sh_less, sh_bincnt;
    float* buf = (float*)scratch;

    const int t = blockIdx.x;
    const int tid = threadIdx.x;
    const int lane = tid & 31;
    const float* srow = S + (size_t)t * VOCAB;
    const float4* srow4 = (const float4*)srow;

    // ---- sample 256 values (stride 125) and bitonic-sort them ----
    samp[tid] = srow[tid * 125];
    __syncthreads();
    for (int k = 2; k <= 256; k <<= 1) {
        for (int j = k >> 1; j > 0; j >>= 1) {
            int ixj = tid ^ j;
            if (ixj > tid) {
                float a = samp[tid], b = samp[ixj];
                bool up = ((tid & k) == 0);
                if ((a > b) == up) { samp[tid] = b; samp[ixj] = a; }
            }
            __syncthreads();
        }
    }

    // ---- sample-select attempts: thr = 7th, then 25th smallest sample ----
    int n = -1;
    bool need_exact = false;
    for (int attempt = 0; attempt < 2; attempt++) {
        float thr = samp[attempt == 0 ? 6 : 24];
        if (tid == 0) sh_cnt = 0;
        __syncthreads();
        for (int i = tid; i < VOCAB / 4; i += 256) {
            float4 v = srow4[i];
            if (v.x <= thr) { unsigned p = atomicAdd(&sh_cnt, 1u); if (p < TK_CAP) buf[p] = v.x; }
            if (v.y <= thr) { unsigned p = atomicAdd(&sh_cnt, 1u); if (p < TK_CAP) buf[p] = v.y; }
            if (v.z <= thr) { unsigned p = atomicAdd(&sh_cnt, 1u); if (p < TK_CAP) buf[p] = v.z; }
            if (v.w <= thr) { unsigned p = atomicAdd(&sh_cnt, 1u); if (p < TK_CAP) buf[p] = v.w; }
        }
        __syncthreads();
        n = (int)sh_cnt;
        if (n > TK_CAP) { need_exact = true; break; }   // overflow: buf incomplete
        if (n >= KSEL) break;                            // success
        if (attempt == 1) need_exact = true;             // still too few: exact path
        __syncthreads();
    }

    // ---- exact radix-select fallback (rare / adversarial) ----
    if (need_exact) {
        uint32_t* hist = scratch;
        const int shifts[3] = {20, 8, 0};
        const int nbins[3]  = {4096, 4096, 256};
        unsigned int P = 0;
        int lessTotal = 0;
        int gShift = 20;

        for (int level = 0; level < 3; level++) {
            const int shift = shifts[level];
            const int bins = nbins[level];
            const unsigned int mask = bins - 1;
            const int prevShift = (level > 0) ? shifts[level - 1] : 32;

            __syncthreads();
            for (int i = tid; i < bins; i += 256) hist[i] = 0;
            __syncthreads();

            for (int j = tid; j < VOCAB; j += 256) {
                unsigned int key = flip_key(srow[j]);
                bool match = (level == 0) || ((key >> prevShift) == P);
                int bin = match ? (int)((key >> shift) & mask) : -1;
                unsigned int grp = __match_any_sync(0xFFFFFFFFu, bin);
                int leader = __ffs(grp) - 1;
                if (lane == leader && bin >= 0)
                    atomicAdd(&hist[bin], __popc(grp));
            }
            __syncthreads();

            const int cs = bins >> 8;
            unsigned int mysum = 0;
            for (int b = 0; b < cs; b++) mysum += hist[tid * cs + b];
            csum[tid] = mysum;
            __syncthreads();
            #pragma unroll
            for (int off = 1; off < 256; off <<= 1) {
                unsigned int v = (tid >= off) ? csum[tid - off] : 0u;
                __syncthreads();
                csum[tid] += v;
                __syncthreads();
            }
            unsigned int incl = csum[tid];
            unsigned int excl = incl - mysum;
            const unsigned int R = (unsigned int)(KSEL - lessTotal);
            if (excl < R && R <= incl) {
                unsigned int cum = excl;
                for (int b = 0; b < cs; b++) {
                    unsigned int c = hist[tid * cs + b];
                    if (cum + c >= R) {
                        sh_bin = tid * cs + b;
                        sh_less = cum;
                        sh_bincnt = c;
                        break;
                    }
                    cum += c;
                }
            }
            __syncthreads();

            P = (level == 0) ? sh_bin : ((P << (prevShift - shift)) | sh_bin);
            lessTotal += (int)sh_less;
            gShift = shift;
            unsigned int cand = (unsigned int)lessTotal + sh_bincnt;
            __syncthreads();
            if (cand <= TK_CAP || level == 2) break;
        }

        if (tid == 0) sh_cnt = 0;
        __syncthreads();
        for (int j = tid; j < VOCAB; j += 256) {
            float d = srow[j];
            unsigned int key = flip_key(d);
            if ((key >> gShift) <= P) {
                unsigned int p = atomicAdd(&sh_cnt, 1u);
                if (p < TK_CAP) buf[p] = d;
            }
        }
        __syncthreads();
        n = (int)min(sh_cnt, (unsigned int)TK_CAP);
    }

    // ---- sort candidates ascending, emit first 128 ----
    int m = KSEL;
    while (m < n) m <<= 1;
    for (int i = n + tid; i < m; i += 256) buf[i] = __int_as_float(0x7F800000);
    __syncthreads();

    for (int ksz = 2; ksz <= m; ksz <<= 1) {
        for (int j2 = ksz >> 1; j2 > 0; j2 >>= 1) {
            for (int i = tid; i < m; i += 256) {
                int ixj = i ^ j2;
                if (ixj > i) {
                    float a = buf[i];
                    float b = buf[ixj];
                    bool up = ((i & ksz) == 0);
                    if ((a > b) == up) { buf[i] = b; buf[ixj] = a; }
                }
            }
            __syncthreads();
        }
    }

    if (tid < KSEL) out[(size_t)t * KSEL + tid] = buf[tid];
}

// ---------------------------------------------------------------------------
// Launch
// ---------------------------------------------------------------------------
extern "C" void kernel_launch(void* const* d_in, const int* in_sizes, int n_in,
                              void* d_out, int out_size) {
    const float* x = (const float*)d_in[0];   // [4096, 1024]
    const float* w = (const float*)d_in[1];   // [32000, 1024]
    float* out = (float*)d_out;               // [4096, 128]

    float *dist, *xsq, *bsq;
    __nv_bfloat16 *xb, *wb;
    cudaGetSymbolAddress((void**)&dist, g_dist);
    cudaGetSymbolAddress((void**)&xsq, g_xsq);
    cudaGetSymbolAddress((void**)&bsq, g_bsq);
    cudaGetSymbolAddress((void**)&xb, g_xb);
    cudaGetSymbolAddress((void**)&wb, g_wb);

    prep_kernel<<<TOKENS, 256>>>(x, xb, xsq);
    prep_kernel<<<VOCAB, 256>>>(w, wb, bsq);

    cudaFuncSetAttribute(gemm_dist_tc_kernel,
                         cudaFuncAttributeMaxDynamicSharedMemorySize, SM_TOTAL);
    dim3 grid(TOKENS / BM, VOCAB / BN);  // (32, 250)
    gemm_dist_tc_kernel<<<grid, 256, SM_TOTAL>>>(xb, wb, xsq, bsq, dist);

    topk_kernel<<<TOKENS, 256>>>(dist, out);
}